// round 16
// baseline (speedup 1.0000x reference)
#include <cuda_runtime.h>
#include <cuda_bf16.h>
#include <cstdint>
#include <math.h>

// ---------------------------------------------------------------------------
// FractalAttention3D — fused attention via mma.sync bf16 (2-way hi/lo split).
//   8-warp (2m x 4n) tiling, paired n-tiles sharing A fragments in registers,
//   phase order repr->con->off with combine folded into stage tails,
//   XOR-swizzled 128B shared-memory rows, cp.async double buffering.
//   Family-portable PTX only (sm_80+). Round 16 submission: functionally
//   identical to R14/R15 (prep_base MLP=8 + feat_mma occupancy-2 cap);
//   header comment changed to bust any content-addressed build cache.
// ---------------------------------------------------------------------------

#define NR 13824
#define ND 1728
#define E_DIM 512
#define F_DIM 512
#define DF_W 64
#define LOGIT_SCALE 0.25f
#define INV_SQRT_H 0.08838834764831843f
#define MAX_CONTRAST 1.8f
#define EXP_SHIFT 30.0f

#define BM 96                 // 144 CTAs ~ one wave
#define BN 64
#define NPAIRS 13             // tiles 0..25 in pairs; tile 26 solo
#define PAIR_STAGES (NPAIRS * 8)   // 104
#define TOT_STAGES (PAIR_STAGES + 8) // 112
#define NTHREADS 256          // 8 warps: 2m x 4n grid of 48x16 warp tiles

// -------- device scratch (static; no cudaMalloc allowed) --------
__device__ __align__(16) float g_br[F_DIM];
__device__ __align__(16) float g_bd[F_DIM];
__device__ __align__(16) __nv_bfloat16 g_Wrth[(size_t)F_DIM * F_DIM];
__device__ __align__(16) __nv_bfloat16 g_Wrtl[(size_t)F_DIM * F_DIM];
__device__ __align__(16) __nv_bfloat16 g_Wdth[(size_t)F_DIM * F_DIM];
__device__ __align__(16) __nv_bfloat16 g_Wdtl[(size_t)F_DIM * F_DIM];
__device__ __align__(16) __nv_bfloat16 g_RBh[(size_t)NR * E_DIM];
__device__ __align__(16) __nv_bfloat16 g_RBl[(size_t)NR * E_DIM];
__device__ __align__(16) __nv_bfloat16 g_DBh[(size_t)ND * E_DIM];
__device__ __align__(16) __nv_bfloat16 g_DBl[(size_t)ND * E_DIM];
__device__ __align__(16) __nv_bfloat16 g_RFh[(size_t)NR * F_DIM];
__device__ __align__(16) __nv_bfloat16 g_RFl[(size_t)NR * F_DIM];
__device__ __align__(16) __nv_bfloat16 g_DFh[(size_t)ND * F_DIM];
__device__ __align__(16) __nv_bfloat16 g_DFl[(size_t)ND * F_DIM];
__device__ __align__(16) __nv_bfloat16 g_PDth[(size_t)DF_W * ND];  // pooled^T hi
__device__ __align__(16) __nv_bfloat16 g_PDtl[(size_t)DF_W * ND];

// ---------------- attention smem (2-buf lockstep, paired B) ----------------
#define AST 12288            // 96*128
#define BST 8192             // 64*128
#define SM_A   0             // 2 bufs x (hi,lo) = 4*AST = 49152
#define SM_B   49152         // 2 bufs x (hi0,lo0,hi1,lo1) = 8*BST = 65536
#define SM_WC0 114688        // hi+lo = 2*AST = 24576
#define SM_WC1 139264        // 24576
#define SM_DF0 163840        // hi+lo = 2*BST = 16384
#define SM_DF1 180224        // 16384
#define SM_RW  196608        // 4*96*4 = 1536
#define SM_RO  198144        // 1536
#define SM_TOTAL 199680

// feat_mma smem: 2 bufs -> 4*AST + 4*BST
#define SM2_TOTAL 81920

// swizzled byte offset of (row, 16B-chunk c) within a 128B-row tile
__device__ __forceinline__ uint32_t sw_off(int row, int c) {
    return (uint32_t)(row * 128 + ((c ^ (row & 7)) * 16));
}

// ---------------- PTX helpers ----------------
__device__ __forceinline__ uint32_t smem_u32(const void* p) {
    uint32_t a;
    asm("{ .reg .u64 t; cvta.to.shared.u64 t, %1; cvt.u32.u64 %0, t; }" : "=r"(a) : "l"(p));
    return a;
}
__device__ __forceinline__ void cp16(uint32_t dst, const void* src) {
    asm volatile("cp.async.cg.shared.global [%0], [%1], 16;" :: "r"(dst), "l"(src));
}
#define CP_COMMIT() asm volatile("cp.async.commit_group;" ::: "memory")
#define CP_WAIT0()  asm volatile("cp.async.wait_group 0;" ::: "memory")
#define CP_WAIT1()  asm volatile("cp.async.wait_group 1;" ::: "memory")

__device__ __forceinline__ void ldsm4(uint32_t& r0, uint32_t& r1, uint32_t& r2, uint32_t& r3,
                                      uint32_t addr) {
    asm volatile("ldmatrix.sync.aligned.m8n8.x4.shared.b16 {%0,%1,%2,%3}, [%4];"
                 : "=r"(r0), "=r"(r1), "=r"(r2), "=r"(r3) : "r"(addr));
}
__device__ __forceinline__ void mma_bf16(float* c, const uint32_t* a, uint32_t b0, uint32_t b1) {
    asm("mma.sync.aligned.m16n8k16.row.col.f32.bf16.bf16.f32 "
        "{%0,%1,%2,%3}, {%4,%5,%6,%7}, {%8,%9}, {%0,%1,%2,%3};"
        : "+f"(c[0]), "+f"(c[1]), "+f"(c[2]), "+f"(c[3])
        : "r"(a[0]), "r"(a[1]), "r"(a[2]), "r"(a[3]), "r"(b0), "r"(b1));
}
__device__ __forceinline__ float fast_tanh(float x) {
    float e = __expf(-2.0f * x);
    return __fdividef(2.0f, e + 1.0f) - 1.0f;
}

// ---------------------------------------------------------------------------
// prep kernels
// ---------------------------------------------------------------------------
__global__ void prep_weights(
    const float* __restrict__ Wrp, const float* __restrict__ brp,
    const float* __restrict__ Wdp, const float* __restrict__ bdp,
    const float* __restrict__ Wrc, const float* __restrict__ brc,
    const float* __restrict__ Wdc, const float* __restrict__ bdc,
    const float* __restrict__ Wro, const float* __restrict__ bro,
    const float* __restrict__ Wdo, const float* __restrict__ bdo)
{
    int e = blockIdx.x, j = threadIdx.x;
    float wr, wd;
    if (j < 256)      { wr = Wrp[e * 256 + j] * LOGIT_SCALE; wd = Wdp[e * 256 + j]; }
    else if (j < 384) { wr = Wrc[e * 128 + (j - 256)];       wd = Wdc[e * 128 + (j - 256)]; }
    else              { wr = Wro[e * 128 + (j - 384)];       wd = Wdo[e * 128 + (j - 384)]; }
    size_t toff = (size_t)j * F_DIM + e;
    __nv_bfloat16 h = __float2bfloat16(wr);
    g_Wrth[toff] = h;
    g_Wrtl[toff] = __float2bfloat16(wr - __bfloat162float(h));
    h = __float2bfloat16(wd);
    g_Wdth[toff] = h;
    g_Wdtl[toff] = __float2bfloat16(wd - __bfloat162float(h));
    if (e == 0) {
        float br, bd;
        if (j < 256)      { br = brp[j] * LOGIT_SCALE; bd = bdp[j]; }
        else if (j < 384) { br = brc[j - 256];         bd = bdc[j - 256]; }
        else              { br = bro[j - 384];         bd = bdo[j - 384]; }
        g_br[j] = br;
        g_bd[j] = bd;
    }
}

__global__ void prep_pd(const float* __restrict__ pooled) {
    int n = blockIdx.x, d = threadIdx.x;
    float v = pooled[(size_t)n * DF_W + d];
    __nv_bfloat16 h = __float2bfloat16(v);
    g_PDth[(size_t)d * ND + n] = h;
    g_PDtl[(size_t)d * ND + n] = __float2bfloat16(v - __bfloat162float(h));
}

// 16 elements/thread; all 8 float4 loads issued before compute (MLP=8)
template <bool RANGE>
__global__ void prep_base(const float* __restrict__ lat, const float* __restrict__ pos)
{
    __nv_bfloat16* __restrict__ OH = RANGE ? g_RBh : g_DBh;
    __nv_bfloat16* __restrict__ OL = RANGE ? g_RBl : g_DBl;
    size_t i = ((size_t)blockIdx.x * blockDim.x + threadIdx.x) * 16;
    float4 a[4], b[4];
#pragma unroll
    for (int q = 0; q < 4; q++) a[q] = *(const float4*)(lat + i + q * 4);
#pragma unroll
    for (int q = 0; q < 4; q++) b[q] = *(const float4*)(pos + i + q * 4);
#pragma unroll
    for (int q = 0; q < 4; q++) {
        float v[4] = {a[q].x + b[q].x, a[q].y + b[q].y, a[q].z + b[q].z, a[q].w + b[q].w};
        __nv_bfloat16 hb[4], lb[4];
#pragma unroll
        for (int j = 0; j < 4; j++) {
            hb[j] = __float2bfloat16(v[j]);
            lb[j] = __float2bfloat16(v[j] - __bfloat162float(hb[j]));
        }
        *(uint2*)(OH + i + q * 4) = *(uint2*)hb;
        *(uint2*)(OL + i + q * 4) = *(uint2*)lb;
    }
}

// ---------------------------------------------------------------------------
// Fragment loads for one k16 slice, swizzled layout.
// ---------------------------------------------------------------------------
__device__ __forceinline__ void ld_a_frags(
    uint32_t (&ah)[3][4], uint32_t (&al)[3][4],
    uint32_t aH, uint32_t aL, int mrow0, int l, int kc)
{
    const int a7 = l & 7;
    const int ar = l & 15;
    const uint32_t aChunk = (uint32_t)((((l >> 4) + kc) ^ a7) * 16);
#pragma unroll
    for (int mt = 0; mt < 3; mt++) {
        uint32_t off = (uint32_t)((mrow0 + mt * 16 + ar) * 128) + aChunk;
        ldsm4(ah[mt][0], ah[mt][1], ah[mt][2], ah[mt][3], aH + off);
        ldsm4(al[mt][0], al[mt][1], al[mt][2], al[mt][3], aL + off);
    }
}
__device__ __forceinline__ void ld_b_frags(
    uint32_t (&bh)[4], uint32_t (&bl)[4],
    uint32_t bH, uint32_t bL, int ncol0, int l, int kc)
{
    const int a7 = l & 7;
    int brow = ncol0 + ((l >> 4) & 1) * 8 + (l & 7);
    uint32_t off = (uint32_t)(brow * 128)
                 + (uint32_t)(((((l >> 3) & 1) + kc) ^ a7) * 16);
    ldsm4(bh[0], bh[1], bh[2], bh[3], bH + off);
    ldsm4(bl[0], bl[1], bl[2], bl[3], bL + off);
}

// single-tile 96x64x64 stage (also used for epilogue + solo tile)
__device__ __forceinline__ void mma_one(
    float (&acc)[3][2][4], uint32_t aH, uint32_t aL, uint32_t bH, uint32_t bL,
    int mrow0, int ncol0, int l)
{
#pragma unroll
    for (int k16 = 0; k16 < 4; k16++) {
        uint32_t ah[3][4], al[3][4], bh[4], bl[4];
        ld_a_frags(ah, al, aH, aL, mrow0, l, k16 * 2);
        ld_b_frags(bh, bl, bH, bL, ncol0, l, k16 * 2);
#pragma unroll
        for (int mt = 0; mt < 3; mt++)
#pragma unroll
            for (int nf = 0; nf < 2; nf++) {
                const int ri = nf * 2;
                mma_bf16(acc[mt][nf], ah[mt], bh[ri], bh[ri + 1]);
                mma_bf16(acc[mt][nf], ah[mt], bl[ri], bl[ri + 1]);
                mma_bf16(acc[mt][nf], al[mt], bh[ri], bh[ri + 1]);
            }
    }
}

// paired stage: A fragments loaded once, both tiles' mma issued from them
__device__ __forceinline__ void mma_pair(
    float (&a0)[3][2][4], float (&a1)[3][2][4],
    uint32_t aH, uint32_t aL, uint32_t bB,   // bB = base of [hi0,lo0,hi1,lo1]
    int mrow0, int ncol0, int l)
{
#pragma unroll
    for (int k16 = 0; k16 < 4; k16++) {
        uint32_t ah[3][4], al[3][4], b0h[4], b0l[4], b1h[4], b1l[4];
        ld_a_frags(ah, al, aH, aL, mrow0, l, k16 * 2);
        ld_b_frags(b0h, b0l, bB + 0 * BST, bB + 1 * BST, ncol0, l, k16 * 2);
        ld_b_frags(b1h, b1l, bB + 2 * BST, bB + 3 * BST, ncol0, l, k16 * 2);
#pragma unroll
        for (int mt = 0; mt < 3; mt++)
#pragma unroll
            for (int nf = 0; nf < 2; nf++) {
                const int ri = nf * 2;
                mma_bf16(a0[mt][nf], ah[mt], b0h[ri], b0h[ri + 1]);
                mma_bf16(a0[mt][nf], ah[mt], b0l[ri], b0l[ri + 1]);
                mma_bf16(a0[mt][nf], al[mt], b0h[ri], b0h[ri + 1]);
                mma_bf16(a1[mt][nf], ah[mt], b1h[ri], b1h[ri + 1]);
                mma_bf16(a1[mt][nf], ah[mt], b1l[ri], b1l[ri + 1]);
                mma_bf16(a1[mt][nf], al[mt], b1h[ri], b1h[ri + 1]);
            }
    }
}

// ---------------------------------------------------------------------------
// Kernel 1: feature GEMM on tensor cores (2-buf; reg-capped for 2 CTAs/SM)
// ---------------------------------------------------------------------------
template <bool RANGE>
__global__ void __launch_bounds__(NTHREADS, 2) feat_mma()
{
    const __nv_bfloat16* __restrict__ Ah = RANGE ? g_RBh : g_DBh;
    const __nv_bfloat16* __restrict__ Al = RANGE ? g_RBl : g_DBl;
    const __nv_bfloat16* __restrict__ Bh = RANGE ? g_Wrth : g_Wdth;
    const __nv_bfloat16* __restrict__ Bl = RANGE ? g_Wrtl : g_Wdtl;
    const float* __restrict__ bias = RANGE ? g_br : g_bd;
    __nv_bfloat16* __restrict__ OH = RANGE ? g_RFh : g_DFh;
    __nv_bfloat16* __restrict__ OL = RANGE ? g_RFl : g_DFl;

    extern __shared__ char smem[];
    const uint32_t sb0 = smem_u32(smem);
    const int t = threadIdx.x;
    const int w = t >> 5, l = t & 31;
    const int m0 = blockIdx.x * BM;
    const int n0 = blockIdx.y * BN;
    const int mrow0 = (w >> 2) * 48;
    const int ncol0 = (w & 3) * 16;

    auto load_s = [&](int s) {
        const int buf = s & 1;
        const int koff = s * 64;
        const uint32_t aH = sb0 + (buf * 2 + 0) * AST;
        const uint32_t aL = sb0 + (buf * 2 + 1) * AST;
#pragma unroll
        for (int c = t; c < 768; c += NTHREADS) {
            int row = c >> 3, ch = c & 7;
            uint32_t so = sw_off(row, ch);
            size_t go = (size_t)(m0 + row) * E_DIM + koff + ch * 8;
            cp16(aH + so, Ah + go);
            cp16(aL + so, Al + go);
        }
        const uint32_t bH = sb0 + 4 * AST + (buf * 2 + 0) * BST;
        const uint32_t bL = sb0 + 4 * AST + (buf * 2 + 1) * BST;
#pragma unroll
        for (int c = t; c < 512; c += NTHREADS) {
            int row = c >> 3, ch = c & 7;
            uint32_t so = sw_off(row, ch);
            size_t go = (size_t)(n0 + row) * F_DIM + koff + ch * 8;
            cp16(bH + so, Bh + go);
            cp16(bL + so, Bl + go);
        }
    };

    float acc[3][2][4];
#pragma unroll
    for (int i = 0; i < 3; i++)
#pragma unroll
        for (int j = 0; j < 2; j++)
#pragma unroll
            for (int r = 0; r < 4; r++) acc[i][j][r] = 0.0f;

    load_s(0);
    CP_COMMIT();
#pragma unroll 1
    for (int s = 0; s < 8; ++s) {
        if (s < 7) { load_s(s + 1); CP_COMMIT(); CP_WAIT1(); }
        else       { CP_WAIT0(); }
        __syncthreads();
        const int buf = s & 1;
        mma_one(acc, sb0 + (buf * 2 + 0) * AST, sb0 + (buf * 2 + 1) * AST,
                sb0 + 4 * AST + (buf * 2 + 0) * BST, sb0 + 4 * AST + (buf * 2 + 1) * BST,
                mrow0, ncol0, l);
        __syncthreads();
    }

#pragma unroll
    for (int mt = 0; mt < 3; mt++)
#pragma unroll
        for (int nf = 0; nf < 2; nf++)
#pragma unroll
            for (int half = 0; half < 2; half++) {
                int row = mrow0 + mt * 16 + (l >> 2) + 8 * half;
                int col = ncol0 + nf * 8 + 2 * (l & 3);
                float v0 = acc[mt][nf][half * 2 + 0] + bias[n0 + col];
                float v1 = acc[mt][nf][half * 2 + 1] + bias[n0 + col + 1];
                __nv_bfloat16 h0 = __float2bfloat16(v0);
                __nv_bfloat16 h1 = __float2bfloat16(v1);
                __nv_bfloat16 l0 = __float2bfloat16(v0 - __bfloat162float(h0));
                __nv_bfloat16 l1 = __float2bfloat16(v1 - __bfloat162float(h1));
                size_t off = (size_t)(m0 + row) * F_DIM + n0 + col;
                __nv_bfloat16 hp[2] = {h0, h1}, lp[2] = {l0, l1};
                *(uint32_t*)(OH + off) = *(uint32_t*)hp;
                *(uint32_t*)(OL + off) = *(uint32_t*)lp;
            }
}

// ---------------------------------------------------------------------------
// Kernel 2: fused attention — paired tiles, phases repr->con->off
// ---------------------------------------------------------------------------
// phase order: s0-3 repr (koff 0..192), s4-5 con (256,320), s6-7 off (384,448)
__device__ __forceinline__ int stage_koff(int s) {
    return (s < 4) ? (s * 64) : ((s < 6) ? (256 + (s - 4) * 64) : (384 + (s - 6) * 64));
}

// load A slice + B tile(s) for global stage st into buffer st&1
__device__ __forceinline__ void load_stage(uint32_t sb0, int st, int m0, int t) {
    const bool solo = (st >= PAIR_STAGES);
    const int s = solo ? (st - PAIR_STAGES) : (st & 7);
    const int p = st >> 3;
    const int koff = stage_koff(s);
    const int n0 = (solo ? 26 : 2 * p) * BN;
    const int buf = st & 1;
    const uint32_t aH = sb0 + SM_A + (buf * 2 + 0) * AST;
    const uint32_t aL = sb0 + SM_A + (buf * 2 + 1) * AST;
#pragma unroll
    for (int c = t; c < 768; c += NTHREADS) {
        int row = c >> 3, ch = c & 7;
        uint32_t so = sw_off(row, ch);
        size_t go = (size_t)(m0 + row) * F_DIM + koff + ch * 8;
        cp16(aH + so, g_RFh + go);
        cp16(aL + so, g_RFl + go);
    }
    const uint32_t bB = sb0 + SM_B + buf * 4 * BST;
#pragma unroll
    for (int c = t; c < 512; c += NTHREADS) {
        int row = c >> 3, ch = c & 7;
        uint32_t so = sw_off(row, ch);
        size_t go = (size_t)(n0 + row) * F_DIM + koff + ch * 8;
        cp16(bB + 0 * BST + so, g_DFh + go);
        cp16(bB + 1 * BST + so, g_DFl + go);
        if (!solo) {
            size_t go1 = go + (size_t)BN * F_DIM;
            cp16(bB + 2 * BST + so, g_DFh + go1);
            cp16(bB + 3 * BST + so, g_DFl + go1);
        }
    }
}

// load pooled^T tile (hi+lo) into a df slot
__device__ __forceinline__ void load_df(uint32_t sb0, int n0, uint32_t dfBase, int t) {
#pragma unroll
    for (int c = t; c < 512; c += NTHREADS) {
        int row = c >> 3, ch = c & 7;
        uint32_t so = sw_off(row, ch);
        size_t go = (size_t)row * ND + n0 + ch * 8;
        cp16(dfBase + so, g_PDth + go);
        cp16(dfBase + BST + so, g_PDtl + go);
    }
}

__global__ void __launch_bounds__(NTHREADS, 1) attention_kernel(float* __restrict__ out)
{
    extern __shared__ char smem[];
    const uint32_t sb0 = smem_u32(smem);

    const int t = threadIdx.x;
    const int w = t >> 5, l = t & 31;
    const int m0 = blockIdx.x * BM;
    const int mrow0 = (w >> 2) * 48;
    const int ncol0 = (w & 3) * 16;

    float* sRW = (float*)(smem + SM_RW);
    float* sRO = (float*)(smem + SM_RO);

    float ep[3][2][4];
#pragma unroll
    for (int i = 0; i < 3; i++)
#pragma unroll
        for (int j = 0; j < 2; j++)
#pragma unroll
            for (int r = 0; r < 4; r++) ep[i][j][r] = 0.0f;
    float pw[3][2]  = {{0.f,0.f},{0.f,0.f},{0.f,0.f}};
    float pwo[3][2] = {{0.f,0.f},{0.f,0.f},{0.f,0.f}};

    float acc0[3][2][4], acc1[3][2][4];
    float w0[3][2][4], w1[3][2][4];

    load_stage(sb0, 0, m0, t);
    CP_COMMIT();

#pragma unroll 1
    for (int st = 0; st < TOT_STAGES; ++st) {
        const bool solo = (st >= PAIR_STAGES);
        const int s = solo ? (st - PAIR_STAGES) : (st & 7);

        if (st + 1 < TOT_STAGES) {
            load_stage(sb0, st + 1, m0, t);
            if (st + 1 < PAIR_STAGES) {
                if (((st + 1) & 7) == 6) {
                    int p = (st + 1) >> 3;
                    load_df(sb0, 2 * p * BN, sb0 + SM_DF0, t);
                    load_df(sb0, (2 * p + 1) * BN, sb0 + SM_DF1, t);
                }
            } else if (st + 1 == PAIR_STAGES + 6) {
                load_df(sb0, 26 * BN, sb0 + SM_DF0, t);
            }
            CP_COMMIT();
            CP_WAIT1();
        } else {
            CP_WAIT0();
        }
        __syncthreads();

        if (s == 0 || s == 4 || s == 6) {
#pragma unroll
            for (int i = 0; i < 3; i++)
#pragma unroll
                for (int j = 0; j < 2; j++)
#pragma unroll
                    for (int r = 0; r < 4; r++) { acc0[i][j][r] = 0.0f; acc1[i][j][r] = 0.0f; }
        }

        const int buf = st & 1;
        const uint32_t aH = sb0 + SM_A + (buf * 2 + 0) * AST;
        const uint32_t aL = sb0 + SM_A + (buf * 2 + 1) * AST;
        const uint32_t bB = sb0 + SM_B + buf * 4 * BST;
        if (!solo)
            mma_pair(acc0, acc1, aH, aL, bB, mrow0, ncol0, l);
        else
            mma_one(acc0, aH, aL, bB, bB + BST, mrow0, ncol0, l);
        __syncthreads();

        // ---- phase tails ----
        if (s == 3) {            // repr done: w = exp(logit - shift); pw
#pragma unroll
            for (int mt = 0; mt < 3; mt++)
#pragma unroll
                for (int nf = 0; nf < 2; nf++)
#pragma unroll
                    for (int r = 0; r < 4; r++) {
                        float v0 = __expf(acc0[mt][nf][r] - EXP_SHIFT);
                        w0[mt][nf][r] = v0;
                        pw[mt][r >> 1] += v0;
                        if (!solo) {
                            float v1 = __expf(acc1[mt][nf][r] - EXP_SHIFT);
                            w1[mt][nf][r] = v1;
                            pw[mt][r >> 1] += v1;
                        }
                    }
        } else if (s == 5) {     // con done: wc -> smem (bf16 hi/lo)
#pragma unroll
            for (int mt = 0; mt < 3; mt++)
#pragma unroll
                for (int nf = 0; nf < 2; nf++)
#pragma unroll
                    for (int r = 0; r < 4; r++) {
                        int row = mrow0 + mt * 16 + (l >> 2) + 8 * (r >> 1);
                        int col = ncol0 + nf * 8 + 2 * (l & 3) + (r & 1);
                        uint32_t so = sw_off(row, col >> 3) + (uint32_t)((col & 7) * 2);
                        float wc0 = w0[mt][nf][r]
                                  * (fast_tanh(acc0[mt][nf][r] * INV_SQRT_H) * MAX_CONTRAST);
                        __nv_bfloat16 h = __float2bfloat16(wc0);
                        *(__nv_bfloat16*)(smem + SM_WC0 + so) = h;
                        *(__nv_bfloat16*)(smem + SM_WC0 + AST + so) =
                            __float2bfloat16(wc0 - __bfloat162float(h));
                        if (!solo) {
                            float wc1 = w1[mt][nf][r]
                                      * (fast_tanh(acc1[mt][nf][r] * INV_SQRT_H) * MAX_CONTRAST);
                            h = __float2bfloat16(wc1);
                            *(__nv_bfloat16*)(smem + SM_WC1 + so) = h;
                            *(__nv_bfloat16*)(smem + SM_WC1 + AST + so) =
                                __float2bfloat16(wc1 - __bfloat162float(h));
                        }
                    }
        } else if (s == 7) {     // off done: pwo; then epilogue(s)
#pragma unroll
            for (int mt = 0; mt < 3; mt++)
#pragma unroll
                for (int nf = 0; nf < 2; nf++)
#pragma unroll
                    for (int r = 0; r < 4; r++) {
                        pwo[mt][r >> 1] += w0[mt][nf][r]
                                         * fast_tanh(acc0[mt][nf][r] * INV_SQRT_H);
                        if (!solo)
                            pwo[mt][r >> 1] += w1[mt][nf][r]
                                             * fast_tanh(acc1[mt][nf][r] * INV_SQRT_H);
                    }
            __syncthreads();
            mma_one(ep, sb0 + SM_WC0, sb0 + SM_WC0 + AST,
                    sb0 + SM_DF0, sb0 + SM_DF0 + BST, mrow0, ncol0, l);
            if (!solo)
                mma_one(ep, sb0 + SM_WC1, sb0 + SM_WC1 + AST,
                        sb0 + SM_DF1, sb0 + SM_DF1 + BST, mrow0, ncol0, l);
        }
    }

    // ---- row-sum reduce: lanes (xor 1,2) then across the 4 n-warps ----
#pragma unroll
    for (int mt = 0; mt < 3; mt++)
#pragma unroll
        for (int h = 0; h < 2; h++) {
            pw[mt][h]  += __shfl_xor_sync(0xffffffffu, pw[mt][h], 1);
            pw[mt][h]  += __shfl_xor_sync(0xffffffffu, pw[mt][h], 2);
            pwo[mt][h] += __shfl_xor_sync(0xffffffffu, pwo[mt][h], 1);
            pwo[mt][h] += __shfl_xor_sync(0xffffffffu, pwo[mt][h], 2);
        }
    if ((l & 3) == 0) {
        const int wq = w & 3;
#pragma unroll
        for (int mt = 0; mt < 3; mt++)
#pragma unroll
            for (int h = 0; h < 2; h++) {
                int row = mrow0 + mt * 16 + (l >> 2) + 8 * h;
                sRW[wq * 96 + row] = pw[mt][h];
                sRO[wq * 96 + row] = pwo[mt][h];
            }
    }
    __syncthreads();

    // ---- final: out = (ep + sum(w*off)) / sum(w) ----
#pragma unroll
    for (int mt = 0; mt < 3; mt++)
#pragma unroll
        for (int nf = 0; nf < 2; nf++)
#pragma unroll
            for (int half = 0; half < 2; half++) {
                int row = mrow0 + mt * 16 + (l >> 2) + 8 * half;
                int col = ncol0 + nf * 8 + 2 * (l & 3);
                float sw  = sRW[row] + sRW[96 + row] + sRW[192 + row] + sRW[288 + row];
                float swo = sRO[row] + sRO[96 + row] + sRO[192 + row] + sRO[288 + row];
                float inv = 1.0f / sw;
                float2 v;
                v.x = (ep[mt][nf][half * 2 + 0] + swo) * inv;
                v.y = (ep[mt][nf][half * 2 + 1] + swo) * inv;
                *(float2*)(out + (size_t)(m0 + row) * DF_W + col) = v;
            }
}

// ---------------------------------------------------------------------------
// kernel_launch — kernel launches only (graph-capture clean)
// ---------------------------------------------------------------------------
extern "C" void kernel_launch(void* const* d_in, const int* in_sizes, int n_in,
                              void* d_out, int out_size)
{
    const float* pooled = (const float*)d_in[0];
    const float* rl     = (const float*)d_in[1];
    const float* dl     = (const float*)d_in[2];
    const float* rp     = (const float*)d_in[3];
    const float* dp     = (const float*)d_in[4];
    const float* Wrp    = (const float*)d_in[5];
    const float* brp    = (const float*)d_in[6];
    const float* Wdp    = (const float*)d_in[7];
    const float* bdp    = (const float*)d_in[8];
    const float* Wrc    = (const float*)d_in[9];
    const float* brc    = (const float*)d_in[10];
    const float* Wdc    = (const float*)d_in[11];
    const float* bdc    = (const float*)d_in[12];
    const float* Wro    = (const float*)d_in[13];
    const float* bro    = (const float*)d_in[14];
    const float* Wdo    = (const float*)d_in[15];
    const float* bdo    = (const float*)d_in[16];
    float* out = (float*)d_out;

    prep_weights<<<512, 512>>>(Wrp, brp, Wdp, bdp, Wrc, brc, Wdc, bdc,
                               Wro, bro, Wdo, bdo);
    prep_pd<<<ND, DF_W>>>(pooled);
    prep_base<true><<<(NR * E_DIM / 16) / 256, 256>>>(rl, rp);    // 1728 blocks
    prep_base<false><<<(ND * E_DIM / 16) / 256, 256>>>(dl, dp);   // 216 blocks

    cudaFuncSetAttribute(feat_mma<false>,
                         cudaFuncAttributeMaxDynamicSharedMemorySize, SM2_TOTAL);
    cudaFuncSetAttribute(feat_mma<true>,
                         cudaFuncAttributeMaxDynamicSharedMemorySize, SM2_TOTAL);
    dim3 gridD(ND / BM, F_DIM / BN);   // 18 x 8
    feat_mma<false><<<gridD, NTHREADS, SM2_TOTAL>>>();
    dim3 gridR(NR / BM, F_DIM / BN);   // 144 x 8
    feat_mma<true><<<gridR, NTHREADS, SM2_TOTAL>>>();

    cudaFuncSetAttribute(attention_kernel,
                         cudaFuncAttributeMaxDynamicSharedMemorySize, SM_TOTAL);
    attention_kernel<<<NR / BM, NTHREADS, SM_TOTAL>>>(out);
}

// round 17
// speedup vs baseline: 1.0021x; 1.0021x over previous
#include <cuda_runtime.h>
#include <cuda_bf16.h>
#include <cstdint>
#include <math.h>

// ---------------------------------------------------------------------------
// FractalAttention3D — mma.sync bf16 (2-way split), 8-warp tiling,
//   paired n-tiles with A-fragment register reuse, phases repr->con->off
//   folded into stage tails. XOR-swizzled 128B smem rows. sm_80+ PTX only.
//   R17: R13 baseline + MLP-8 prep_base for the RANGE variant only;
//   feat_mma back to launch_bounds(256,1).
// ---------------------------------------------------------------------------

#define NR 13824
#define ND 1728
#define E_DIM 512
#define F_DIM 512
#define DF_W 64
#define LOGIT_SCALE 0.25f
#define INV_SQRT_H 0.08838834764831843f
#define MAX_CONTRAST 1.8f
#define EXP_SHIFT 30.0f

#define BM 96                 // 144 CTAs ~ one wave
#define BN 64
#define NPAIRS 13             // tiles 0..25 in pairs; tile 26 solo
#define PAIR_STAGES (NPAIRS * 8)   // 104
#define TOT_STAGES (PAIR_STAGES + 8) // 112
#define NTHREADS 256          // 8 warps: 2m x 4n grid of 48x16 warp tiles

// -------- device scratch (static; no cudaMalloc allowed) --------
__device__ __align__(16) float g_br[F_DIM];
__device__ __align__(16) float g_bd[F_DIM];
__device__ __align__(16) __nv_bfloat16 g_Wrth[(size_t)F_DIM * F_DIM];
__device__ __align__(16) __nv_bfloat16 g_Wrtl[(size_t)F_DIM * F_DIM];
__device__ __align__(16) __nv_bfloat16 g_Wdth[(size_t)F_DIM * F_DIM];
__device__ __align__(16) __nv_bfloat16 g_Wdtl[(size_t)F_DIM * F_DIM];
__device__ __align__(16) __nv_bfloat16 g_RBh[(size_t)NR * E_DIM];
__device__ __align__(16) __nv_bfloat16 g_RBl[(size_t)NR * E_DIM];
__device__ __align__(16) __nv_bfloat16 g_DBh[(size_t)ND * E_DIM];
__device__ __align__(16) __nv_bfloat16 g_DBl[(size_t)ND * E_DIM];
__device__ __align__(16) __nv_bfloat16 g_RFh[(size_t)NR * F_DIM];
__device__ __align__(16) __nv_bfloat16 g_RFl[(size_t)NR * F_DIM];
__device__ __align__(16) __nv_bfloat16 g_DFh[(size_t)ND * F_DIM];
__device__ __align__(16) __nv_bfloat16 g_DFl[(size_t)ND * F_DIM];
__device__ __align__(16) __nv_bfloat16 g_PDth[(size_t)DF_W * ND];  // pooled^T hi
__device__ __align__(16) __nv_bfloat16 g_PDtl[(size_t)DF_W * ND];

// ---------------- attention smem (2-buf lockstep, paired B) ----------------
#define AST 12288            // 96*128
#define BST 8192             // 64*128
#define SM_A   0             // 2 bufs x (hi,lo) = 4*AST = 49152
#define SM_B   49152         // 2 bufs x (hi0,lo0,hi1,lo1) = 8*BST = 65536
#define SM_WC0 114688        // hi+lo = 2*AST = 24576
#define SM_WC1 139264        // 24576
#define SM_DF0 163840        // hi+lo = 2*BST = 16384
#define SM_DF1 180224        // 16384
#define SM_RW  196608        // 4*96*4 = 1536
#define SM_RO  198144        // 1536
#define SM_TOTAL 199680

// feat_mma smem: 2 bufs -> 4*AST + 4*BST
#define SM2_TOTAL 81920

// swizzled byte offset of (row, 16B-chunk c) within a 128B-row tile
__device__ __forceinline__ uint32_t sw_off(int row, int c) {
    return (uint32_t)(row * 128 + ((c ^ (row & 7)) * 16));
}

// ---------------- PTX helpers ----------------
__device__ __forceinline__ uint32_t smem_u32(const void* p) {
    uint32_t a;
    asm("{ .reg .u64 t; cvta.to.shared.u64 t, %1; cvt.u32.u64 %0, t; }" : "=r"(a) : "l"(p));
    return a;
}
__device__ __forceinline__ void cp16(uint32_t dst, const void* src) {
    asm volatile("cp.async.cg.shared.global [%0], [%1], 16;" :: "r"(dst), "l"(src));
}
#define CP_COMMIT() asm volatile("cp.async.commit_group;" ::: "memory")
#define CP_WAIT0()  asm volatile("cp.async.wait_group 0;" ::: "memory")
#define CP_WAIT1()  asm volatile("cp.async.wait_group 1;" ::: "memory")

__device__ __forceinline__ void ldsm4(uint32_t& r0, uint32_t& r1, uint32_t& r2, uint32_t& r3,
                                      uint32_t addr) {
    asm volatile("ldmatrix.sync.aligned.m8n8.x4.shared.b16 {%0,%1,%2,%3}, [%4];"
                 : "=r"(r0), "=r"(r1), "=r"(r2), "=r"(r3) : "r"(addr));
}
__device__ __forceinline__ void mma_bf16(float* c, const uint32_t* a, uint32_t b0, uint32_t b1) {
    asm("mma.sync.aligned.m16n8k16.row.col.f32.bf16.bf16.f32 "
        "{%0,%1,%2,%3}, {%4,%5,%6,%7}, {%8,%9}, {%0,%1,%2,%3};"
        : "+f"(c[0]), "+f"(c[1]), "+f"(c[2]), "+f"(c[3])
        : "r"(a[0]), "r"(a[1]), "r"(a[2]), "r"(a[3]), "r"(b0), "r"(b1));
}
__device__ __forceinline__ float fast_tanh(float x) {
    float e = __expf(-2.0f * x);
    return __fdividef(2.0f, e + 1.0f) - 1.0f;
}

// ---------------------------------------------------------------------------
// prep kernels
// ---------------------------------------------------------------------------
__global__ void prep_weights(
    const float* __restrict__ Wrp, const float* __restrict__ brp,
    const float* __restrict__ Wdp, const float* __restrict__ bdp,
    const float* __restrict__ Wrc, const float* __restrict__ brc,
    const float* __restrict__ Wdc, const float* __restrict__ bdc,
    const float* __restrict__ Wro, const float* __restrict__ bro,
    const float* __restrict__ Wdo, const float* __restrict__ bdo)
{
    int e = blockIdx.x, j = threadIdx.x;
    float wr, wd;
    if (j < 256)      { wr = Wrp[e * 256 + j] * LOGIT_SCALE; wd = Wdp[e * 256 + j]; }
    else if (j < 384) { wr = Wrc[e * 128 + (j - 256)];       wd = Wdc[e * 128 + (j - 256)]; }
    else              { wr = Wro[e * 128 + (j - 384)];       wd = Wdo[e * 128 + (j - 384)]; }
    size_t toff = (size_t)j * F_DIM + e;
    __nv_bfloat16 h = __float2bfloat16(wr);
    g_Wrth[toff] = h;
    g_Wrtl[toff] = __float2bfloat16(wr - __bfloat162float(h));
    h = __float2bfloat16(wd);
    g_Wdth[toff] = h;
    g_Wdtl[toff] = __float2bfloat16(wd - __bfloat162float(h));
    if (e == 0) {
        float br, bd;
        if (j < 256)      { br = brp[j] * LOGIT_SCALE; bd = bdp[j]; }
        else if (j < 384) { br = brc[j - 256];         bd = bdc[j - 256]; }
        else              { br = bro[j - 384];         bd = bdo[j - 384]; }
        g_br[j] = br;
        g_bd[j] = bd;
    }
}

__global__ void prep_pd(const float* __restrict__ pooled) {
    int n = blockIdx.x, d = threadIdx.x;
    float v = pooled[(size_t)n * DF_W + d];
    __nv_bfloat16 h = __float2bfloat16(v);
    g_PDth[(size_t)d * ND + n] = h;
    g_PDtl[(size_t)d * ND + n] = __float2bfloat16(v - __bfloat162float(h));
}

// base = lat + pos -> bf16 hi/lo.
// RANGE: 16 elem/thread, all 8 float4 loads front-batched (MLP=8; 1728 blocks).
// DOMAIN: 4 elem/thread (864 blocks — keeps occupancy on the small variant).
template <bool RANGE>
__global__ void prep_base(const float* __restrict__ lat, const float* __restrict__ pos)
{
    __nv_bfloat16* __restrict__ OH = RANGE ? g_RBh : g_DBh;
    __nv_bfloat16* __restrict__ OL = RANGE ? g_RBl : g_DBl;
    if (RANGE) {
        size_t i = ((size_t)blockIdx.x * blockDim.x + threadIdx.x) * 16;
        float4 a[4], b[4];
#pragma unroll
        for (int q = 0; q < 4; q++) a[q] = *(const float4*)(lat + i + q * 4);
#pragma unroll
        for (int q = 0; q < 4; q++) b[q] = *(const float4*)(pos + i + q * 4);
#pragma unroll
        for (int q = 0; q < 4; q++) {
            float v[4] = {a[q].x + b[q].x, a[q].y + b[q].y, a[q].z + b[q].z, a[q].w + b[q].w};
            __nv_bfloat16 hb[4], lb[4];
#pragma unroll
            for (int j = 0; j < 4; j++) {
                hb[j] = __float2bfloat16(v[j]);
                lb[j] = __float2bfloat16(v[j] - __bfloat162float(hb[j]));
            }
            *(uint2*)(OH + i + q * 4) = *(uint2*)hb;
            *(uint2*)(OL + i + q * 4) = *(uint2*)lb;
        }
    } else {
        size_t i = ((size_t)blockIdx.x * blockDim.x + threadIdx.x) * 4;
        float4 a = *(const float4*)(lat + i);
        float4 b = *(const float4*)(pos + i);
        float v[4] = {a.x + b.x, a.y + b.y, a.z + b.z, a.w + b.w};
        __nv_bfloat16 hb[4], lb[4];
#pragma unroll
        for (int j = 0; j < 4; j++) {
            hb[j] = __float2bfloat16(v[j]);
            lb[j] = __float2bfloat16(v[j] - __bfloat162float(hb[j]));
        }
        *(uint2*)(OH + i) = *(uint2*)hb;
        *(uint2*)(OL + i) = *(uint2*)lb;
    }
}

// ---------------------------------------------------------------------------
// Fragment loads for one k16 slice, swizzled layout.
// ---------------------------------------------------------------------------
__device__ __forceinline__ void ld_a_frags(
    uint32_t (&ah)[3][4], uint32_t (&al)[3][4],
    uint32_t aH, uint32_t aL, int mrow0, int l, int kc)
{
    const int a7 = l & 7;
    const int ar = l & 15;
    const uint32_t aChunk = (uint32_t)((((l >> 4) + kc) ^ a7) * 16);
#pragma unroll
    for (int mt = 0; mt < 3; mt++) {
        uint32_t off = (uint32_t)((mrow0 + mt * 16 + ar) * 128) + aChunk;
        ldsm4(ah[mt][0], ah[mt][1], ah[mt][2], ah[mt][3], aH + off);
        ldsm4(al[mt][0], al[mt][1], al[mt][2], al[mt][3], aL + off);
    }
}
__device__ __forceinline__ void ld_b_frags(
    uint32_t (&bh)[4], uint32_t (&bl)[4],
    uint32_t bH, uint32_t bL, int ncol0, int l, int kc)
{
    const int a7 = l & 7;
    int brow = ncol0 + ((l >> 4) & 1) * 8 + (l & 7);
    uint32_t off = (uint32_t)(brow * 128)
                 + (uint32_t)(((((l >> 3) & 1) + kc) ^ a7) * 16);
    ldsm4(bh[0], bh[1], bh[2], bh[3], bH + off);
    ldsm4(bl[0], bl[1], bl[2], bl[3], bL + off);
}

// single-tile 96x64x64 stage (also used for epilogue + solo tile)
__device__ __forceinline__ void mma_one(
    float (&acc)[3][2][4], uint32_t aH, uint32_t aL, uint32_t bH, uint32_t bL,
    int mrow0, int ncol0, int l)
{
#pragma unroll
    for (int k16 = 0; k16 < 4; k16++) {
        uint32_t ah[3][4], al[3][4], bh[4], bl[4];
        ld_a_frags(ah, al, aH, aL, mrow0, l, k16 * 2);
        ld_b_frags(bh, bl, bH, bL, ncol0, l, k16 * 2);
#pragma unroll
        for (int mt = 0; mt < 3; mt++)
#pragma unroll
            for (int nf = 0; nf < 2; nf++) {
                const int ri = nf * 2;
                mma_bf16(acc[mt][nf], ah[mt], bh[ri], bh[ri + 1]);
                mma_bf16(acc[mt][nf], ah[mt], bl[ri], bl[ri + 1]);
                mma_bf16(acc[mt][nf], al[mt], bh[ri], bh[ri + 1]);
            }
    }
}

// paired stage: A fragments loaded once, both tiles' mma issued from them
__device__ __forceinline__ void mma_pair(
    float (&a0)[3][2][4], float (&a1)[3][2][4],
    uint32_t aH, uint32_t aL, uint32_t bB,   // bB = base of [hi0,lo0,hi1,lo1]
    int mrow0, int ncol0, int l)
{
#pragma unroll
    for (int k16 = 0; k16 < 4; k16++) {
        uint32_t ah[3][4], al[3][4], b0h[4], b0l[4], b1h[4], b1l[4];
        ld_a_frags(ah, al, aH, aL, mrow0, l, k16 * 2);
        ld_b_frags(b0h, b0l, bB + 0 * BST, bB + 1 * BST, ncol0, l, k16 * 2);
        ld_b_frags(b1h, b1l, bB + 2 * BST, bB + 3 * BST, ncol0, l, k16 * 2);
#pragma unroll
        for (int mt = 0; mt < 3; mt++)
#pragma unroll
            for (int nf = 0; nf < 2; nf++) {
                const int ri = nf * 2;
                mma_bf16(a0[mt][nf], ah[mt], b0h[ri], b0h[ri + 1]);
                mma_bf16(a0[mt][nf], ah[mt], b0l[ri], b0l[ri + 1]);
                mma_bf16(a0[mt][nf], al[mt], b0h[ri], b0h[ri + 1]);
                mma_bf16(a1[mt][nf], ah[mt], b1h[ri], b1h[ri + 1]);
                mma_bf16(a1[mt][nf], ah[mt], b1l[ri], b1l[ri + 1]);
                mma_bf16(a1[mt][nf], al[mt], b1h[ri], b1h[ri + 1]);
            }
    }
}

// ---------------------------------------------------------------------------
// Kernel 1: feature GEMM on tensor cores (2-buf; R13 launch bounds)
// ---------------------------------------------------------------------------
template <bool RANGE>
__global__ void __launch_bounds__(NTHREADS, 1) feat_mma()
{
    const __nv_bfloat16* __restrict__ Ah = RANGE ? g_RBh : g_DBh;
    const __nv_bfloat16* __restrict__ Al = RANGE ? g_RBl : g_DBl;
    const __nv_bfloat16* __restrict__ Bh = RANGE ? g_Wrth : g_Wdth;
    const __nv_bfloat16* __restrict__ Bl = RANGE ? g_Wrtl : g_Wdtl;
    const float* __restrict__ bias = RANGE ? g_br : g_bd;
    __nv_bfloat16* __restrict__ OH = RANGE ? g_RFh : g_DFh;
    __nv_bfloat16* __restrict__ OL = RANGE ? g_RFl : g_DFl;

    extern __shared__ char smem[];
    const uint32_t sb0 = smem_u32(smem);
    const int t = threadIdx.x;
    const int w = t >> 5, l = t & 31;
    const int m0 = blockIdx.x * BM;
    const int n0 = blockIdx.y * BN;
    const int mrow0 = (w >> 2) * 48;
    const int ncol0 = (w & 3) * 16;

    auto load_s = [&](int s) {
        const int buf = s & 1;
        const int koff = s * 64;
        const uint32_t aH = sb0 + (buf * 2 + 0) * AST;
        const uint32_t aL = sb0 + (buf * 2 + 1) * AST;
#pragma unroll
        for (int c = t; c < 768; c += NTHREADS) {
            int row = c >> 3, ch = c & 7;
            uint32_t so = sw_off(row, ch);
            size_t go = (size_t)(m0 + row) * E_DIM + koff + ch * 8;
            cp16(aH + so, Ah + go);
            cp16(aL + so, Al + go);
        }
        const uint32_t bH = sb0 + 4 * AST + (buf * 2 + 0) * BST;
        const uint32_t bL = sb0 + 4 * AST + (buf * 2 + 1) * BST;
#pragma unroll
        for (int c = t; c < 512; c += NTHREADS) {
            int row = c >> 3, ch = c & 7;
            uint32_t so = sw_off(row, ch);
            size_t go = (size_t)(n0 + row) * F_DIM + koff + ch * 8;
            cp16(bH + so, Bh + go);
            cp16(bL + so, Bl + go);
        }
    };

    float acc[3][2][4];
#pragma unroll
    for (int i = 0; i < 3; i++)
#pragma unroll
        for (int j = 0; j < 2; j++)
#pragma unroll
            for (int r = 0; r < 4; r++) acc[i][j][r] = 0.0f;

    load_s(0);
    CP_COMMIT();
#pragma unroll 1
    for (int s = 0; s < 8; ++s) {
        if (s < 7) { load_s(s + 1); CP_COMMIT(); CP_WAIT1(); }
        else       { CP_WAIT0(); }
        __syncthreads();
        const int buf = s & 1;
        mma_one(acc, sb0 + (buf * 2 + 0) * AST, sb0 + (buf * 2 + 1) * AST,
                sb0 + 4 * AST + (buf * 2 + 0) * BST, sb0 + 4 * AST + (buf * 2 + 1) * BST,
                mrow0, ncol0, l);
        __syncthreads();
    }

#pragma unroll
    for (int mt = 0; mt < 3; mt++)
#pragma unroll
        for (int nf = 0; nf < 2; nf++)
#pragma unroll
            for (int half = 0; half < 2; half++) {
                int row = mrow0 + mt * 16 + (l >> 2) + 8 * half;
                int col = ncol0 + nf * 8 + 2 * (l & 3);
                float v0 = acc[mt][nf][half * 2 + 0] + bias[n0 + col];
                float v1 = acc[mt][nf][half * 2 + 1] + bias[n0 + col + 1];
                __nv_bfloat16 h0 = __float2bfloat16(v0);
                __nv_bfloat16 h1 = __float2bfloat16(v1);
                __nv_bfloat16 l0 = __float2bfloat16(v0 - __bfloat162float(h0));
                __nv_bfloat16 l1 = __float2bfloat16(v1 - __bfloat162float(h1));
                size_t off = (size_t)(m0 + row) * F_DIM + n0 + col;
                __nv_bfloat16 hp[2] = {h0, h1}, lp[2] = {l0, l1};
                *(uint32_t*)(OH + off) = *(uint32_t*)hp;
                *(uint32_t*)(OL + off) = *(uint32_t*)lp;
            }
}

// ---------------------------------------------------------------------------
// Kernel 2: fused attention — paired tiles, phases repr->con->off
// ---------------------------------------------------------------------------
// phase order: s0-3 repr (koff 0..192), s4-5 con (256,320), s6-7 off (384,448)
__device__ __forceinline__ int stage_koff(int s) {
    return (s < 4) ? (s * 64) : ((s < 6) ? (256 + (s - 4) * 64) : (384 + (s - 6) * 64));
}

// load A slice + B tile(s) for global stage st into buffer st&1
__device__ __forceinline__ void load_stage(uint32_t sb0, int st, int m0, int t) {
    const bool solo = (st >= PAIR_STAGES);
    const int s = solo ? (st - PAIR_STAGES) : (st & 7);
    const int p = st >> 3;
    const int koff = stage_koff(s);
    const int n0 = (solo ? 26 : 2 * p) * BN;
    const int buf = st & 1;
    const uint32_t aH = sb0 + SM_A + (buf * 2 + 0) * AST;
    const uint32_t aL = sb0 + SM_A + (buf * 2 + 1) * AST;
#pragma unroll
    for (int c = t; c < 768; c += NTHREADS) {
        int row = c >> 3, ch = c & 7;
        uint32_t so = sw_off(row, ch);
        size_t go = (size_t)(m0 + row) * F_DIM + koff + ch * 8;
        cp16(aH + so, g_RFh + go);
        cp16(aL + so, g_RFl + go);
    }
    const uint32_t bB = sb0 + SM_B + buf * 4 * BST;
#pragma unroll
    for (int c = t; c < 512; c += NTHREADS) {
        int row = c >> 3, ch = c & 7;
        uint32_t so = sw_off(row, ch);
        size_t go = (size_t)(n0 + row) * F_DIM + koff + ch * 8;
        cp16(bB + 0 * BST + so, g_DFh + go);
        cp16(bB + 1 * BST + so, g_DFl + go);
        if (!solo) {
            size_t go1 = go + (size_t)BN * F_DIM;
            cp16(bB + 2 * BST + so, g_DFh + go1);
            cp16(bB + 3 * BST + so, g_DFl + go1);
        }
    }
}

// load pooled^T tile (hi+lo) into a df slot
__device__ __forceinline__ void load_df(uint32_t sb0, int n0, uint32_t dfBase, int t) {
#pragma unroll
    for (int c = t; c < 512; c += NTHREADS) {
        int row = c >> 3, ch = c & 7;
        uint32_t so = sw_off(row, ch);
        size_t go = (size_t)row * ND + n0 + ch * 8;
        cp16(dfBase + so, g_PDth + go);
        cp16(dfBase + BST + so, g_PDtl + go);
    }
}

__global__ void __launch_bounds__(NTHREADS, 1) attention_kernel(float* __restrict__ out)
{
    extern __shared__ char smem[];
    const uint32_t sb0 = smem_u32(smem);

    const int t = threadIdx.x;
    const int w = t >> 5, l = t & 31;
    const int m0 = blockIdx.x * BM;
    const int mrow0 = (w >> 2) * 48;
    const int ncol0 = (w & 3) * 16;

    float* sRW = (float*)(smem + SM_RW);
    float* sRO = (float*)(smem + SM_RO);

    float ep[3][2][4];
#pragma unroll
    for (int i = 0; i < 3; i++)
#pragma unroll
        for (int j = 0; j < 2; j++)
#pragma unroll
            for (int r = 0; r < 4; r++) ep[i][j][r] = 0.0f;
    float pw[3][2]  = {{0.f,0.f},{0.f,0.f},{0.f,0.f}};
    float pwo[3][2] = {{0.f,0.f},{0.f,0.f},{0.f,0.f}};

    float acc0[3][2][4], acc1[3][2][4];
    float w0[3][2][4], w1[3][2][4];

    load_stage(sb0, 0, m0, t);
    CP_COMMIT();

#pragma unroll 1
    for (int st = 0; st < TOT_STAGES; ++st) {
        const bool solo = (st >= PAIR_STAGES);
        const int s = solo ? (st - PAIR_STAGES) : (st & 7);

        if (st + 1 < TOT_STAGES) {
            load_stage(sb0, st + 1, m0, t);
            if (st + 1 < PAIR_STAGES) {
                if (((st + 1) & 7) == 6) {
                    int p = (st + 1) >> 3;
                    load_df(sb0, 2 * p * BN, sb0 + SM_DF0, t);
                    load_df(sb0, (2 * p + 1) * BN, sb0 + SM_DF1, t);
                }
            } else if (st + 1 == PAIR_STAGES + 6) {
                load_df(sb0, 26 * BN, sb0 + SM_DF0, t);
            }
            CP_COMMIT();
            CP_WAIT1();
        } else {
            CP_WAIT0();
        }
        __syncthreads();

        if (s == 0 || s == 4 || s == 6) {
#pragma unroll
            for (int i = 0; i < 3; i++)
#pragma unroll
                for (int j = 0; j < 2; j++)
#pragma unroll
                    for (int r = 0; r < 4; r++) { acc0[i][j][r] = 0.0f; acc1[i][j][r] = 0.0f; }
        }

        const int buf = st & 1;
        const uint32_t aH = sb0 + SM_A + (buf * 2 + 0) * AST;
        const uint32_t aL = sb0 + SM_A + (buf * 2 + 1) * AST;
        const uint32_t bB = sb0 + SM_B + buf * 4 * BST;
        if (!solo)
            mma_pair(acc0, acc1, aH, aL, bB, mrow0, ncol0, l);
        else
            mma_one(acc0, aH, aL, bB, bB + BST, mrow0, ncol0, l);
        __syncthreads();

        // ---- phase tails ----
        if (s == 3) {            // repr done: w = exp(logit - shift); pw
#pragma unroll
            for (int mt = 0; mt < 3; mt++)
#pragma unroll
                for (int nf = 0; nf < 2; nf++)
#pragma unroll
                    for (int r = 0; r < 4; r++) {
                        float v0 = __expf(acc0[mt][nf][r] - EXP_SHIFT);
                        w0[mt][nf][r] = v0;
                        pw[mt][r >> 1] += v0;
                        if (!solo) {
                            float v1 = __expf(acc1[mt][nf][r] - EXP_SHIFT);
                            w1[mt][nf][r] = v1;
                            pw[mt][r >> 1] += v1;
                        }
                    }
        } else if (s == 5) {     // con done: wc -> smem (bf16 hi/lo)
#pragma unroll
            for (int mt = 0; mt < 3; mt++)
#pragma unroll
                for (int nf = 0; nf < 2; nf++)
#pragma unroll
                    for (int r = 0; r < 4; r++) {
                        int row = mrow0 + mt * 16 + (l >> 2) + 8 * (r >> 1);
                        int col = ncol0 + nf * 8 + 2 * (l & 3) + (r & 1);
                        uint32_t so = sw_off(row, col >> 3) + (uint32_t)((col & 7) * 2);
                        float wc0 = w0[mt][nf][r]
                                  * (fast_tanh(acc0[mt][nf][r] * INV_SQRT_H) * MAX_CONTRAST);
                        __nv_bfloat16 h = __float2bfloat16(wc0);
                        *(__nv_bfloat16*)(smem + SM_WC0 + so) = h;
                        *(__nv_bfloat16*)(smem + SM_WC0 + AST + so) =
                            __float2bfloat16(wc0 - __bfloat162float(h));
                        if (!solo) {
                            float wc1 = w1[mt][nf][r]
                                      * (fast_tanh(acc1[mt][nf][r] * INV_SQRT_H) * MAX_CONTRAST);
                            h = __float2bfloat16(wc1);
                            *(__nv_bfloat16*)(smem + SM_WC1 + so) = h;
                            *(__nv_bfloat16*)(smem + SM_WC1 + AST + so) =
                                __float2bfloat16(wc1 - __bfloat162float(h));
                        }
                    }
        } else if (s == 7) {     // off done: pwo; then epilogue(s)
#pragma unroll
            for (int mt = 0; mt < 3; mt++)
#pragma unroll
                for (int nf = 0; nf < 2; nf++)
#pragma unroll
                    for (int r = 0; r < 4; r++) {
                        pwo[mt][r >> 1] += w0[mt][nf][r]
                                         * fast_tanh(acc0[mt][nf][r] * INV_SQRT_H);
                        if (!solo)
                            pwo[mt][r >> 1] += w1[mt][nf][r]
                                             * fast_tanh(acc1[mt][nf][r] * INV_SQRT_H);
                    }
            __syncthreads();
            mma_one(ep, sb0 + SM_WC0, sb0 + SM_WC0 + AST,
                    sb0 + SM_DF0, sb0 + SM_DF0 + BST, mrow0, ncol0, l);
            if (!solo)
                mma_one(ep, sb0 + SM_WC1, sb0 + SM_WC1 + AST,
                        sb0 + SM_DF1, sb0 + SM_DF1 + BST, mrow0, ncol0, l);
        }
    }

    // ---- row-sum reduce: lanes (xor 1,2) then across the 4 n-warps ----
#pragma unroll
    for (int mt = 0; mt < 3; mt++)
#pragma unroll
        for (int h = 0; h < 2; h++) {
            pw[mt][h]  += __shfl_xor_sync(0xffffffffu, pw[mt][h], 1);
            pw[mt][h]  += __shfl_xor_sync(0xffffffffu, pw[mt][h], 2);
            pwo[mt][h] += __shfl_xor_sync(0xffffffffu, pwo[mt][h], 1);
            pwo[mt][h] += __shfl_xor_sync(0xffffffffu, pwo[mt][h], 2);
        }
    if ((l & 3) == 0) {
        const int wq = w & 3;
#pragma unroll
        for (int mt = 0; mt < 3; mt++)
#pragma unroll
            for (int h = 0; h < 2; h++) {
                int row = mrow0 + mt * 16 + (l >> 2) + 8 * h;
                sRW[wq * 96 + row] = pw[mt][h];
                sRO[wq * 96 + row] = pwo[mt][h];
            }
    }
    __syncthreads();

    // ---- final: out = (ep + sum(w*off)) / sum(w) ----
#pragma unroll
    for (int mt = 0; mt < 3; mt++)
#pragma unroll
        for (int nf = 0; nf < 2; nf++)
#pragma unroll
            for (int half = 0; half < 2; half++) {
                int row = mrow0 + mt * 16 + (l >> 2) + 8 * half;
                int col = ncol0 + nf * 8 + 2 * (l & 3);
                float sw  = sRW[row] + sRW[96 + row] + sRW[192 + row] + sRW[288 + row];
                float swo = sRO[row] + sRO[96 + row] + sRO[192 + row] + sRO[288 + row];
                float inv = 1.0f / sw;
                float2 v;
                v.x = (ep[mt][nf][half * 2 + 0] + swo) * inv;
                v.y = (ep[mt][nf][half * 2 + 1] + swo) * inv;
                *(float2*)(out + (size_t)(m0 + row) * DF_W + col) = v;
            }
}

// ---------------------------------------------------------------------------
// kernel_launch — kernel launches only (graph-capture clean)
// ---------------------------------------------------------------------------
extern "C" void kernel_launch(void* const* d_in, const int* in_sizes, int n_in,
                              void* d_out, int out_size)
{
    const float* pooled = (const float*)d_in[0];
    const float* rl     = (const float*)d_in[1];
    const float* dl     = (const float*)d_in[2];
    const float* rp     = (const float*)d_in[3];
    const float* dp     = (const float*)d_in[4];
    const float* Wrp    = (const float*)d_in[5];
    const float* brp    = (const float*)d_in[6];
    const float* Wdp    = (const float*)d_in[7];
    const float* bdp    = (const float*)d_in[8];
    const float* Wrc    = (const float*)d_in[9];
    const float* brc    = (const float*)d_in[10];
    const float* Wdc    = (const float*)d_in[11];
    const float* bdc    = (const float*)d_in[12];
    const float* Wro    = (const float*)d_in[13];
    const float* bro    = (const float*)d_in[14];
    const float* Wdo    = (const float*)d_in[15];
    const float* bdo    = (const float*)d_in[16];
    float* out = (float*)d_out;

    prep_weights<<<512, 512>>>(Wrp, brp, Wdp, bdp, Wrc, brc, Wdc, bdc,
                               Wro, bro, Wdo, bdo);
    prep_pd<<<ND, DF_W>>>(pooled);
    prep_base<true><<<(NR * E_DIM / 16) / 256, 256>>>(rl, rp);    // 1728 blocks, MLP=8
    prep_base<false><<<(ND * E_DIM / 4) / 256, 256>>>(dl, dp);    // 864 blocks

    cudaFuncSetAttribute(feat_mma<false>,
                         cudaFuncAttributeMaxDynamicSharedMemorySize, SM2_TOTAL);
    cudaFuncSetAttribute(feat_mma<true>,
                         cudaFuncAttributeMaxDynamicSharedMemorySize, SM2_TOTAL);
    dim3 gridD(ND / BM, F_DIM / BN);   // 18 x 8
    feat_mma<false><<<gridD, NTHREADS, SM2_TOTAL>>>();
    dim3 gridR(NR / BM, F_DIM / BN);   // 144 x 8
    feat_mma<true><<<gridR, NTHREADS, SM2_TOTAL>>>();

    cudaFuncSetAttribute(attention_kernel,
                         cudaFuncAttributeMaxDynamicSharedMemorySize, SM_TOTAL);
    attention_kernel<<<NR / BM, NTHREADS, SM_TOTAL>>>(out);
}